// round 16
// baseline (speedup 1.0000x reference)
#include <cuda_runtime.h>
#include <cuda_bf16.h>
#include <cstdint>

#define BB 32
#define NN 256
#define DD 128
#define NEG_MASK (-9000000.0f)
#define LEAK 0.2f

// Scratch for masked relation scores (allowed: __device__ globals)
__device__ float g_s1[BB * NN * NN];
__device__ float g_s2[BB * NN * NN];

typedef unsigned long long ull;

// ---------------------------------------------------------------------------
// f32x2 packed-math helpers (combine kernel)
// ---------------------------------------------------------------------------
__device__ __forceinline__ ull fma2(ull a, ull b, ull c) {
    ull d;
    asm("fma.rn.f32x2 %0, %1, %2, %3;" : "=l"(d) : "l"(a), "l"(b), "l"(c));
    return d;
}
__device__ __forceinline__ ull pack2(float lo, float hi) {
    ull d;
    asm("mov.b64 %0, {%1, %2};" : "=l"(d) : "f"(lo), "f"(hi));
    return d;
}
__device__ __forceinline__ void unpack2(ull v, float& lo, float& hi) {
    asm("mov.b64 {%0, %1}, %2;" : "=f"(lo), "=f"(hi) : "l"(v));
}

// ---------------------------------------------------------------------------
// mma.sync helpers (compute_100 baseline — no tcgen05 in this toolchain)
// ---------------------------------------------------------------------------
__device__ __forceinline__ uint32_t smem_u32(const void* p) {
    uint32_t a;
    asm("{ .reg .u64 t; cvta.to.shared.u64 t, %1; cvt.u32.u64 %0, t; }"
        : "=r"(a) : "l"(p));
    return a;
}

__device__ __forceinline__ void ldsm4(uint32_t* r, uint32_t addr) {
    asm volatile("ldmatrix.sync.aligned.m8n8.x4.shared.b16 {%0,%1,%2,%3}, [%4];"
                 : "=r"(r[0]), "=r"(r[1]), "=r"(r[2]), "=r"(r[3]) : "r"(addr));
}
__device__ __forceinline__ void ldsm2(uint32_t* r, uint32_t addr) {
    asm volatile("ldmatrix.sync.aligned.m8n8.x2.shared.b16 {%0,%1}, [%2];"
                 : "=r"(r[0]), "=r"(r[1]) : "r"(addr));
}
__device__ __forceinline__ void mma16816(float* c, const uint32_t* a,
                                         const uint32_t* b) {
    asm volatile(
        "mma.sync.aligned.m16n8k16.row.col.f32.bf16.bf16.f32 "
        "{%0,%1,%2,%3}, {%4,%5,%6,%7}, {%8,%9}, {%0,%1,%2,%3};"
        : "+f"(c[0]), "+f"(c[1]), "+f"(c[2]), "+f"(c[3])
        : "r"(a[0]), "r"(a[1]), "r"(a[2]), "r"(a[3]), "r"(b[0]), "r"(b[1]));
}

// Split f32 pair into bf16-hi pair + bf16-lo (residual) pair, packed u32 each.
__device__ __forceinline__ void split2(float p0, float p1,
                                       uint32_t& hi, uint32_t& lo) {
    asm("cvt.rn.satfinite.bf16x2.f32 %0, %1, %2;" : "=r"(hi) : "f"(p1), "f"(p0));
    float f0 = __uint_as_float(hi << 16);
    float f1 = __uint_as_float(hi & 0xffff0000u);
    float r0 = p0 - f0, r1 = p1 - f1;
    asm("cvt.rn.satfinite.bf16x2.f32 %0, %1, %2;" : "=r"(lo) : "f"(r1), "f"(r0));
}

// ---------------------------------------------------------------------------
// Kernel A (mma.sync, row-panel): E_r = (H .* w_r) @ H^T, split-bf16 x3.
// (unchanged — R15-measured 37.3us)
// ---------------------------------------------------------------------------
#define PIT 272
#define SA_OFF 0
#define SB_OFF (4 * 2 * 32 * PIT)          // 69632
#define SMEMB (SB_OFF + 2 * 64 * PIT)      // 104448

extern __shared__ unsigned char smraw[];

__global__ __launch_bounds__(256, 2) void scores_mma_kernel(
    const float* __restrict__ sem, const float* __restrict__ strv,
    const int* __restrict__ adj,
    const float* __restrict__ aw, const float* __restrict__ swt)
{
    const int i0 = blockIdx.x * 32, b = blockIdx.y;
    const int tid = threadIdx.x, w = tid >> 5, lane = tid & 31;
    const int rr = w & 3, nh = w >> 2;

    const uint32_t smbase = smem_u32(smraw);

    for (int e = 0; e < 2; e++) {
        const float* h = e ? strv : sem;
        const float* wm = e ? swt : aw;
        float* gs = e ? g_s2 : g_s1;

        __syncthreads();   // prior readers of A region done

        // ---- stage A panel once: p = h_i[d]*w_r[d], hi/lo split, full K ----
        {
            const int k2 = tid & 63;
            const int mb = tid >> 6;
            float2 wreg[4];
#pragma unroll
            for (int r = 0; r < 4; r++)
                wreg[r] = *(const float2*)&wm[r * DD + 2 * k2];
#pragma unroll
            for (int q = 0; q < 8; q++) {
                int m = mb * 8 + q;
                float2 h2 = *(const float2*)&h[((b * NN) + i0 + m) * DD + 2 * k2];
#pragma unroll
                for (int r = 0; r < 4; r++) {
                    uint32_t hi, lo;
                    split2(h2.x * wreg[r].x, h2.y * wreg[r].y, hi, lo);
                    *(uint32_t*)(smraw + SA_OFF + ((r * 2 + 0) * 32 + m) * PIT + k2 * 4) = hi;
                    *(uint32_t*)(smraw + SA_OFF + ((r * 2 + 1) * 32 + m) * PIT + k2 * 4) = lo;
                }
            }
        }

        for (int jt = 0; jt < 4; jt++) {
            const int j0 = jt * 64;
            __syncthreads();

            // ---- stage B tile: h_j hi/lo split, full K ----
#pragma unroll
            for (int q = 0; q < 16; q++) {
                int t = tid + 256 * q;
                int n = t >> 6, k2b = t & 63;
                float2 h2 = *(const float2*)&h[((b * NN) + j0 + n) * DD + 2 * k2b];
                uint32_t hi, lo;
                split2(h2.x, h2.y, hi, lo);
                *(uint32_t*)(smraw + SB_OFF + (0 * 64 + n) * PIT + k2b * 4) = hi;
                *(uint32_t*)(smraw + SB_OFF + (1 * 64 + n) * PIT + k2b * 4) = lo;
            }
            __syncthreads();

            // ---- mma mainloop: warp = (rr, nh), 32m x 32n ----
            float c[2][4][4];
#pragma unroll
            for (int mt = 0; mt < 2; mt++)
#pragma unroll
                for (int nt = 0; nt < 4; nt++)
#pragma unroll
                    for (int q = 0; q < 4; q++) c[mt][nt][q] = 0.f;

#pragma unroll 1
            for (int ks = 0; ks < 8; ks++) {
                uint32_t ahi[2][4], alo[2][4];
#pragma unroll
                for (int mt = 0; mt < 2; mt++) {
                    uint32_t ab = smbase + SA_OFF +
                        (uint32_t)(((rr * 2 + 0) * 32 + mt * 16 + (lane & 15)) * PIT +
                                   ks * 32 + (lane >> 4) * 16);
                    ldsm4(ahi[mt], ab);
                    ldsm4(alo[mt], ab + 32 * PIT);
                }
#pragma unroll
                for (int nt = 0; nt < 4; nt++) {
                    uint32_t bb = smbase + SB_OFF +
                        (uint32_t)((nh * 32 + nt * 8 + (lane & 7)) * PIT +
                                   ks * 32 + ((lane >> 3) & 1) * 16);
                    uint32_t bhi[2], blo[2];
                    ldsm2(bhi, bb);
                    ldsm2(blo, bb + 64 * PIT);
#pragma unroll
                    for (int mt = 0; mt < 2; mt++) {
                        mma16816(c[mt][nt], ahi[mt], bhi);
                        mma16816(c[mt][nt], ahi[mt], blo);
                        mma16816(c[mt][nt], alo[mt], bhi);
                    }
                }
            }

            // ---- C -> smem (reuse B region; all mma done) ----
            __syncthreads();
            float* smC = (float*)(smraw + SB_OFF);
#pragma unroll
            for (int mt = 0; mt < 2; mt++)
#pragma unroll
                for (int nt = 0; nt < 4; nt++) {
                    int row0 = mt * 16 + (lane >> 2);
                    int col = nh * 32 + nt * 8 + (lane & 3) * 2;
                    *(float2*)&smC[(rr * 32 + row0) * 66 + col] =
                        make_float2(c[mt][nt][0], c[mt][nt][1]);
                    *(float2*)&smC[(rr * 32 + row0 + 8) * 66 + col] =
                        make_float2(c[mt][nt][2], c[mt][nt][3]);
                }
            __syncthreads();

            // ---- gate by adj, leaky, masked store ----
            const int i = tid >> 3, jg = tid & 7;
            const int* arow = &adj[((b * NN) + i0 + i) * NN + j0 + jg * 8];
            float* orow = gs + ((b * NN) + i0 + i) * NN + j0 + jg * 8;
#pragma unroll
            for (int q = 0; q < 2; q++) {
                int4 a4 = ((const int4*)arow)[q];
                int aa[4] = {a4.x, a4.y, a4.z, a4.w};
                float vv[4];
#pragma unroll
                for (int cc = 0; cc < 4; cc++) {
                    int a = aa[cc];
                    if (a > 0) {
                        float x = smC[((a - 1) * 32 + i) * 66 + jg * 8 + q * 4 + cc];
                        vv[cc] = x >= 0.f ? x : LEAK * x;
                    } else {
                        vv[cc] = NEG_MASK;
                    }
                }
                ((float4*)orow)[q] = make_float4(vv[0], vv[1], vv[2], vv[3]);
            }
        }
    }
}

// ---------------------------------------------------------------------------
// Kernel B v2: split-embed combine. CTA = 16 rows, 8 warps: warps 0-3 run
// embed-1 entmax (4 rows/warp via 8-lane groups), warps 4-7 embed-2.
// X state halves (32 regs) -> 4 CTAs/SM, grid 512 single wave.
// wf phase: embed-1 warps recompute p2 from g_s2 (R6-verified exact).
// ---------------------------------------------------------------------------
__device__ __forceinline__ float gsum8(float v) {
#pragma unroll
    for (int o = 1; o < 8; o <<= 1) v += __shfl_xor_sync(0xffffffffu, v, o);
    return v;
}
__device__ __forceinline__ float gmax8(float v) {
#pragma unroll
    for (int o = 1; o < 8; o <<= 1) v = fmaxf(v, __shfl_xor_sync(0xffffffffu, v, o));
    return v;
}

template <int MODE>
__device__ __forceinline__ float pf(float z, float inv) {
    float t = fmaxf(z, 0.f);
    if (MODE == 2) return t * t;     // alpha = 1.5
    if (MODE == 1) return t;         // alpha = 2.0
    return __powf(t, inv);           // generic
}

template <int MODE>
__device__ __forceinline__ float psum32(const float4* X, float tau, float inv) {
    float4 a = make_float4(0.f, 0.f, 0.f, 0.f);
#pragma unroll
    for (int t = 0; t < 8; t++) {
        a.x += pf<MODE>(X[t].x - tau, inv);
        a.y += pf<MODE>(X[t].y - tau, inv);
        a.z += pf<MODE>(X[t].z - tau, inv);
        a.w += pf<MODE>(X[t].w - tau, inv);
    }
    return (a.x + a.y) + (a.z + a.w);
}

// One entmax instance: load row into X, bisect, return tau & S (X stays live).
template <int MODE>
__device__ __forceinline__ void entmax_one(
    const float* __restrict__ gsrow, float am1, float inv, int s,
    float4* X, float& tauOut, float& Sout)
{
    float mx = -3.4e38f;
#pragma unroll
    for (int t = 0; t < 8; t++) {
        float4 v = ((const float4*)gsrow)[s + 8 * t];
        v.x *= am1; v.y *= am1; v.z *= am1; v.w *= am1;
        X[t] = v;
        mx = fmaxf(mx, fmaxf(fmaxf(v.x, v.y), fmaxf(v.z, v.w)));
    }
    mx = gmax8(mx);

    float tau = mx - 1.f;
    float dm = 1.f - exp2f(-8.f * am1);
    float flo = gsum8(psum32<MODE>(X, tau, inv)) - 1.f;

    const int NBIS = (MODE == 0) ? 30 : 20;
#pragma unroll 1
    for (int it = 0; it < NBIS; it++) {
        dm *= 0.5f;
        float tm = tau + dm;
        float ss = gsum8(psum32<MODE>(X, tm, inv));
        if ((ss - 1.f) * flo >= 0.f) tau = tm;
    }

    Sout = gsum8(psum32<MODE>(X, tau, inv));
    tauOut = tau;
}

// wf phase for embed-1 warps: p1 from X regs, p2 recomputed from g_s2 row.
template <int M1, int M2>
__device__ __forceinline__ void wf_phase(
    const float4* X, const float* __restrict__ g2row,
    float tau1, float inv1, float am1_2, float tau2, float inv2,
    float S1, float S2, int s,
    float4* __restrict__ wrow4, float* __restrict__ wscale_slot)
{
    float s3 = 0.f;
#pragma unroll
    for (int t = 0; t < 8; t++) {
        float4 x2 = ((const float4*)g2row)[s + 8 * t];
        float4 wf;
        wf.x = pf<M1>(X[t].x - tau1, inv1) *
               pf<M2>(__fmul_rn(x2.x, am1_2) - tau2, inv2);
        wf.y = pf<M1>(X[t].y - tau1, inv1) *
               pf<M2>(__fmul_rn(x2.y, am1_2) - tau2, inv2);
        wf.z = pf<M1>(X[t].z - tau1, inv1) *
               pf<M2>(__fmul_rn(x2.z, am1_2) - tau2, inv2);
        wf.w = pf<M1>(X[t].w - tau1, inv1) *
               pf<M2>(__fmul_rn(x2.w, am1_2) - tau2, inv2);
        s3 += (wf.x + wf.y) + (wf.z + wf.w);
        wrow4[s + 8 * t] = wf;
    }
    s3 = gsum8(s3);
    // weight = p1p2/(S1S2) / (s3/(S1S2)+1e-7) = p1p2 / (s3 + 1e-7 S1 S2)
    float scale = 1.f / (s3 + 1e-7f * S1 * S2);
    if (s == 0) *wscale_slot = scale;
}

template <int M1, int M2>
__device__ void combine_work(
    const float* __restrict__ sem, float* __restrict__ out,
    int b, int i0, int tid, float am1_1, float am1_2, float inv1, float inv2,
    float4 (*wsm4)[NN / 4], float* wscale, float (*tauA)[16], float (*SA)[16])
{
    const int w = tid >> 5, lane = tid & 31;
    const int e = w >> 2;               // embed this warp owns
    const int g = lane >> 3, s = lane & 7;
    const int rowLocal = (w & 3) * 4 + g;   // 0..15
    const int row = i0 + rowLocal;

    const float am1 = e ? am1_2 : am1_1;
    const float inv = e ? inv2 : inv1;
    const float* gsrow = (e ? g_s2 : g_s1) + ((b * NN) + row) * NN;

    float4 X[8];
    float tau, S;
    if (e == 0) entmax_one<M1>(gsrow, am1, inv, s, X, tau, S);
    else        entmax_one<M2>(gsrow, am1, inv, s, X, tau, S);
    if (s == 0) { tauA[e][rowLocal] = tau; SA[e][rowLocal] = S; }
    __syncthreads();

    if (e == 0) {
        const float* g2row = g_s2 + ((b * NN) + row) * NN;
        wf_phase<M1, M2>(X, g2row, tau, inv1, am1_2,
                         tauA[1][rowLocal], inv2, S, SA[1][rowLocal], s,
                         wsm4[rowLocal], &wscale[rowLocal]);
    }
    __syncthreads();

    // Output GEMV: thread -> d4 = tid&31, 2 rows = (tid>>5)*2 + k (f32x2)
    const int d4 = tid & 31, rbase = (tid >> 5) * 2;
    ull accA[2], accB[2];
#pragma unroll
    for (int k = 0; k < 2; k++) { accA[k] = 0ull; accB[k] = 0ull; }

    const ulonglong2* semb2 = (const ulonglong2*)(sem + b * NN * DD);
    const float* wrow0 = (const float*)wsm4[rbase + 0];
    const float* wrow1 = (const float*)wsm4[rbase + 1];

#pragma unroll 4
    for (int j = 0; j < NN; j++) {
        ulonglong2 vv = semb2[j * 32 + d4];
        ull w0 = pack2(wrow0[j], wrow0[j]);
        ull w1 = pack2(wrow1[j], wrow1[j]);
        accA[0] = fma2(w0, vv.x, accA[0]); accB[0] = fma2(w0, vv.y, accB[0]);
        accA[1] = fma2(w1, vv.x, accA[1]); accB[1] = fma2(w1, vv.y, accB[1]);
    }

#pragma unroll
    for (int k = 0; k < 2; k++) {
        float sc = wscale[rbase + k];
        float4 o;
        unpack2(accA[k], o.x, o.y);
        unpack2(accB[k], o.z, o.w);
        o.x *= sc; o.y *= sc; o.z *= sc; o.w *= sc;
        ((float4*)(out + ((b * NN) + i0 + rbase + k) * DD))[d4] = o;
    }
}

__global__ __launch_bounds__(256, 4) void combine_kernel(
    const float* __restrict__ sem,
    const float* __restrict__ alpha1p, const float* __restrict__ alpha2p,
    float* __restrict__ out)
{
    __shared__ float4 wsm4[16][NN / 4];   // 16 rows x 256 raw weights (16KB)
    __shared__ float wscale[16];
    __shared__ float tauA[2][16];
    __shared__ float SA[2][16];

    const int b = blockIdx.y;
    const int i0 = blockIdx.x * 16;
    const int tid = threadIdx.x;

    float a1 = alpha1p[0], a2 = alpha2p[0];
    float am1_1 = a1 - 1.f, am1_2 = a2 - 1.f;
    float inv1 = 1.f / am1_1, inv2 = 1.f / am1_2;

    int m1 = (fabsf(a1 - 1.5f) < 1e-4f) ? 2 : ((fabsf(a1 - 2.f) < 1e-4f) ? 1 : 0);
    int m2 = (fabsf(a2 - 1.5f) < 1e-4f) ? 2 : ((fabsf(a2 - 2.f) < 1e-4f) ? 1 : 0);

    if (m1 == 2 && m2 == 1)
        combine_work<2, 1>(sem, out, b, i0, tid, am1_1, am1_2, inv1, inv2,
                           wsm4, wscale, tauA, SA);
    else if (m1 == 1 && m2 == 2)
        combine_work<1, 2>(sem, out, b, i0, tid, am1_1, am1_2, inv1, inv2,
                           wsm4, wscale, tauA, SA);
    else if (m1 == 2 && m2 == 2)
        combine_work<2, 2>(sem, out, b, i0, tid, am1_1, am1_2, inv1, inv2,
                           wsm4, wscale, tauA, SA);
    else if (m1 == 1 && m2 == 1)
        combine_work<1, 1>(sem, out, b, i0, tid, am1_1, am1_2, inv1, inv2,
                           wsm4, wscale, tauA, SA);
    else
        combine_work<0, 0>(sem, out, b, i0, tid, am1_1, am1_2, inv1, inv2,
                           wsm4, wscale, tauA, SA);
}

// ---------------------------------------------------------------------------
extern "C" void kernel_launch(void* const* d_in, const int* in_sizes, int n_in,
                              void* d_out, int out_size)
{
    const float* sem  = (const float*)d_in[0];
    const float* strv = (const float*)d_in[1];
    const int*   adj  = (const int*)d_in[2];
    const float* aw   = (const float*)d_in[3];
    const float* swt  = (const float*)d_in[4];
    const float* a1   = (const float*)d_in[5];
    const float* a2   = (const float*)d_in[6];
    float* out = (float*)d_out;

    cudaFuncSetAttribute(scores_mma_kernel,
                         cudaFuncAttributeMaxDynamicSharedMemorySize, SMEMB);

    scores_mma_kernel<<<dim3(8, BB), 256, SMEMB>>>(sem, strv, adj, aw, swt);
    combine_kernel<<<dim3(NN / 16, BB), 256>>>(sem, a1, a2, out);
}